// round 14
// baseline (speedup 1.0000x reference)
#include <cuda_runtime.h>
#include <math.h>

#define C_DIM 128
#define S_DIM 4096
#define HW 176          // 16 * 11
#define HW4 44          // HW / 4
#define B_SEG 32
#define O_DIM 256
#define OG 8            // o per conv block
#define CQ 4            // c-split factor inside block
#define CC_PER (C_DIM / CQ)   // 32
#define CPIPE 4
#define PART_LEN 44
#define GEM_EPS 1e-6f
#define NEG_INF -3.402823466e38f

// scratch: pooled[b][c][hw]
__device__ float g_pooled[B_SEG * C_DIM * HW];

__device__ __forceinline__ float4 max4(float4 a, float4 b) {
    float4 r;
    r.x = fmaxf(a.x, b.x); r.y = fmaxf(a.y, b.y);
    r.z = fmaxf(a.z, b.z); r.w = fmaxf(a.w, b.w);
    return r;
}
__device__ __forceinline__ unsigned long long pack2(float v) {
    unsigned long long r;
    asm("mov.b64 %0, {%1, %1};" : "=l"(r) : "f"(v));
    return r;
}
__device__ __forceinline__ void unpack2(unsigned long long v, float& lo, float& hi) {
    asm("mov.b64 {%0, %1}, %2;" : "=f"(lo), "=f"(hi) : "l"(v));
}
__device__ __forceinline__ void ffma2(unsigned long long& d,
                                      unsigned long long a, unsigned long long b) {
    asm("fma.rn.f32x2 %0, %1, %2, %0;" : "+l"(d) : "l"(a), "l"(b));
}
// GeM power, fast path for pe == 6.5: (v^3)^2 * sqrt(v).
__device__ __forceinline__ float gem_pow(float x, float pe, bool fast65) {
    float v = fmaxf(x, GEM_EPS);
    if (fast65) {
        float v3 = v * v * v;
        return v3 * v3 * sqrtf(v);
    }
    return exp2f(pe * __log2f(v));
}

// ---------------------------------------------------------------------------
// Kernel 1: ragged segment max — EXACT R7 config, do not touch.
// ---------------------------------------------------------------------------
__global__ void __launch_bounds__(352) seg_max_kernel(
    const float* __restrict__ x, const int* __restrict__ seqL)
{
    int blk = blockIdx.x;
    int b = blk & (B_SEG - 1);
    int c = blk >> 5;

    __shared__ int sh[2];
    __shared__ float4 sm[8 * HW4];

    if (threadIdx.x == 0) {
        int s0 = 0;
        #pragma unroll
        for (int i = 0; i < B_SEG; i++) s0 += (i < b) ? seqL[i] : 0;
        sh[0] = s0;
        sh[1] = seqL[b];
    }
    __syncthreads();

    int tid = threadIdx.x;
    int sg  = tid / HW4;
    int col = tid % HW4;

    int s0  = sh[0];
    int len = sh[1];

    const float4* bp = reinterpret_cast<const float4*>(x)
                     + (size_t)c * (S_DIM * HW4) + (size_t)s0 * HW4 + col;

    float4 m = make_float4(NEG_INF, NEG_INF, NEG_INF, NEG_INF);
    int s = sg;
    for (; s + 56 < len; s += 64) {
        float4 a0 = __ldcs(&bp[(size_t)(s +  0) * HW4]);
        float4 a1 = __ldcs(&bp[(size_t)(s +  8) * HW4]);
        float4 a2 = __ldcs(&bp[(size_t)(s + 16) * HW4]);
        float4 a3 = __ldcs(&bp[(size_t)(s + 24) * HW4]);
        float4 a4 = __ldcs(&bp[(size_t)(s + 32) * HW4]);
        float4 a5 = __ldcs(&bp[(size_t)(s + 40) * HW4]);
        float4 a6 = __ldcs(&bp[(size_t)(s + 48) * HW4]);
        float4 a7 = __ldcs(&bp[(size_t)(s + 56) * HW4]);
        m = max4(m, max4(max4(max4(a0, a1), max4(a2, a3)),
                         max4(max4(a4, a5), max4(a6, a7))));
    }
    for (; s < len; s += 8) {
        m = max4(m, __ldcs(&bp[(size_t)s * HW4]));
    }

    sm[sg * HW4 + col] = m;
    __syncthreads();

    if (tid < HW4) {
        float4 r = sm[tid];
        #pragma unroll
        for (int g = 1; g < 8; g++) r = max4(r, sm[g * HW4 + tid]);
        reinterpret_cast<float4*>(g_pooled)[(size_t)(b * C_DIM + c) * HW4 + tid] = r;
    }
}

// ---------------------------------------------------------------------------
// Kernel 2: conv + GeM. Low loads/MAC AND high block count.
// Grid (32 o-groups of 8, 32 b) = 1024 blocks, 176 threads =
// 4 c-quarters x 44 hw-quads. Thread: 32 cc x (1 LDG.128 + 2 LDS.128 +
// 16 FFMA2) accumulating 4 hw x 8 o; then smem reduce over c-quarters,
// gem_pow, reduce over hw, output.
// ---------------------------------------------------------------------------
__global__ void __launch_bounds__(176) conv_gem_kernel(
    const float* __restrict__ Wmat, const float* __restrict__ p,
    float* __restrict__ out)
{
    __shared__ __align__(16) float ws[C_DIM * OG];    // [c][o], 4 KB
    __shared__ float red[CQ * HW4 * 32];              // 22.5 KB
    __shared__ float red2[HW4 * OG];                  // 1.4 KB
    __shared__ float pp[4];

    int b   = blockIdx.y;
    int o0  = blockIdx.x * OG;
    int tid = threadIdx.x;
    int cq  = tid / HW4;          // c-quarter 0..3
    int q   = tid % HW4;          // hw quad 0..43

    if (tid < 4) pp[tid] = p[tid];
    for (int i = tid; i < C_DIM * OG; i += 176) {
        int cc = i >> 3;
        int j  = i & (OG - 1);
        ws[i] = Wmat[(o0 + j) * C_DIM + cc];
    }
    __syncthreads();

    unsigned long long acc[16];   // [h 0..3][opair 0..3]
    #pragma unroll
    for (int k = 0; k < 16; k++) acc[k] = 0ULL;

    {
        int cbase = cq * CC_PER;
        const float4* pb = reinterpret_cast<const float4*>(
            g_pooled + (size_t)b * C_DIM * HW) + (size_t)cbase * HW4 + q;
        const float* wq = ws + cbase * OG;

        float4 pv[CPIPE];
        #pragma unroll
        for (int j = 0; j < CPIPE; j++)
            pv[j] = __ldg(&pb[(size_t)j * HW4]);

        #pragma unroll
        for (int c0 = 0; c0 < CC_PER; c0 += CPIPE) {
            float4 nv[CPIPE];
            if (c0 + CPIPE < CC_PER) {
                #pragma unroll
                for (int j = 0; j < CPIPE; j++)
                    nv[j] = __ldg(&pb[(size_t)(c0 + CPIPE + j) * HW4]);
            }
            #pragma unroll
            for (int j = 0; j < CPIPE; j++) {
                const ulonglong2* wr = reinterpret_cast<const ulonglong2*>(
                    wq + (c0 + j) * OG);
                ulonglong2 w0 = wr[0];   // o 0..3
                ulonglong2 w1 = wr[1];   // o 4..7
                unsigned long long px = pack2(pv[j].x);
                unsigned long long py = pack2(pv[j].y);
                unsigned long long pz = pack2(pv[j].z);
                unsigned long long pw = pack2(pv[j].w);
                ffma2(acc[ 0], px, w0.x); ffma2(acc[ 1], px, w0.y);
                ffma2(acc[ 2], px, w1.x); ffma2(acc[ 3], px, w1.y);
                ffma2(acc[ 4], py, w0.x); ffma2(acc[ 5], py, w0.y);
                ffma2(acc[ 6], py, w1.x); ffma2(acc[ 7], py, w1.y);
                ffma2(acc[ 8], pz, w0.x); ffma2(acc[ 9], pz, w0.y);
                ffma2(acc[10], pz, w1.x); ffma2(acc[11], pz, w1.y);
                ffma2(acc[12], pw, w0.x); ffma2(acc[13], pw, w0.y);
                ffma2(acc[14], pw, w1.x); ffma2(acc[15], pw, w1.y);
            }
            #pragma unroll
            for (int j = 0; j < CPIPE; j++) pv[j] = nv[j];
        }
    }

    // dump partials: red[cq][q][h*8 + o]
    {
        float* rp = red + (cq * HW4 + q) * 32;
        #pragma unroll
        for (int h = 0; h < 4; h++) {
            #pragma unroll
            for (int k = 0; k < 4; k++) {
                float lo, hi;
                unpack2(acc[h * 4 + k], lo, hi);
                rp[h * 8 + 2 * k + 0] = lo;
                rp[h * 8 + 2 * k + 1] = hi;
            }
        }
    }
    __syncthreads();

    // combine c-quarters, gem_pow, sum over this quad's 4 hw.
    // thread t: q = t%44, handles o = 2*(t/44), 2*(t/44)+1.
    {
        int od  = (tid / HW4) * 2;
        float pe = pp[q / 11];
        bool fast65 = (pe == 6.5f);
        const float* r0 = red + (0 * HW4 + q) * 32;
        const float* r1 = red + (1 * HW4 + q) * 32;
        const float* r2 = red + (2 * HW4 + q) * 32;
        const float* r3 = red + (3 * HW4 + q) * 32;
        float s0 = 0.0f, s1 = 0.0f;
        #pragma unroll
        for (int h = 0; h < 4; h++) {
            int i0 = h * 8 + od;
            float v0 = r0[i0]     + r1[i0]     + r2[i0]     + r3[i0];
            float v1 = r0[i0 + 1] + r1[i0 + 1] + r2[i0 + 1] + r3[i0 + 1];
            s0 += gem_pow(v0, pe, fast65);
            s1 += gem_pow(v1, pe, fast65);
        }
        red2[q * OG + od]     = s0;
        red2[q * OG + od + 1] = s1;
    }
    __syncthreads();

    // 32 threads: (o, part) -> sum 11 quad-partials, final root.
    if (tid < OG * 4) {
        int o    = tid >> 2;
        int part = tid & 3;
        float sum = 0.0f;
        #pragma unroll
        for (int j = 0; j < 11; j++)
            sum += red2[(part * 11 + j) * OG + o];
        float pe = pp[part];
        float mean = sum * (1.0f / (float)PART_LEN);
        float gv = (mean > 0.0f) ? exp2f(__log2f(mean) / pe) : 0.0f;
        out[((size_t)b * O_DIM + o0 + o) * 4 + part] = gv;
    }
}

extern "C" void kernel_launch(void* const* d_in, const int* in_sizes, int n_in,
                              void* d_out, int out_size)
{
    const float* x    = (const float*)d_in[0];
    const int*   seqL = (const int*)d_in[1];
    const float* Wm   = (const float*)d_in[2];
    const float* p    = (const float*)d_in[3];
    float* out = (float*)d_out;

    seg_max_kernel<<<B_SEG * C_DIM, 352>>>(x, seqL);

    dim3 grid2(O_DIM / OG, B_SEG);
    conv_gem_kernel<<<grid2, 176>>>(Wm, p, out);
}

// round 15
// speedup vs baseline: 1.0051x; 1.0051x over previous
#include <cuda_runtime.h>
#include <math.h>

#define C_DIM 128
#define S_DIM 4096
#define HW 176          // 16 * 11
#define HW4 44
#define B_SEG 32
#define O_DIM 256
#define OSLICE 4        // o per conv slice
#define NSLICE 64       // conv slices per b (arrival order >= 64)
#define PART_LEN 44
#define GEM_EPS 1e-6f
#define NEG_INF -3.402823466e38f

__device__ float g_pooled[B_SEG * C_DIM * HW];   // [b][c][hw]
__device__ int   g_cnt[B_SEG];

__device__ __forceinline__ float4 max4(float4 a, float4 b) {
    float4 r;
    r.x = fmaxf(a.x, b.x); r.y = fmaxf(a.y, b.y);
    r.z = fmaxf(a.z, b.z); r.w = fmaxf(a.w, b.w);
    return r;
}
__device__ __forceinline__ unsigned long long pack2(float v) {
    unsigned long long r;
    asm("mov.b64 %0, {%1, %1};" : "=l"(r) : "f"(v));
    return r;
}
__device__ __forceinline__ void unpack2(unsigned long long v, float& lo, float& hi) {
    asm("mov.b64 {%0, %1}, %2;" : "=f"(lo), "=f"(hi) : "l"(v));
}
__device__ __forceinline__ void ffma2(unsigned long long& d,
                                      unsigned long long a, unsigned long long b) {
    asm("fma.rn.f32x2 %0, %1, %2, %0;" : "+l"(d) : "l"(a), "l"(b));
}
// GeM power, fast path for pe == 6.5: (v^3)^2 * sqrt(v).
__device__ __forceinline__ float gem_pow(float x, float pe, bool fast65) {
    float v = fmaxf(x, GEM_EPS);
    if (fast65) {
        float v3 = v * v * v;
        return v3 * v3 * sqrtf(v);
    }
    return exp2f(pe * __log2f(v));
}

__global__ void zero_cnt_kernel() {
    if (threadIdx.x < B_SEG) g_cnt[threadIdx.x] = 0;
}

// ---------------------------------------------------------------------------
// Fused kernel, b-major bid, 5.6 KB smem (single union buffer).
// Phase 1: segment max for (b, c) — identical streaming loop to the 58.7us
// standalone. Publish via threadfence + atomicAdd(cnt[b]).
// Arrival order >= 64: become one of 64 conv slices for b (4 o each).
// Slice is tiny (1 packed acc / thread) so the last-b tail is one parallel
// wave of ~64 small blocks (~5us) instead of a ~30us serial crawl.
// ---------------------------------------------------------------------------
__global__ void __launch_bounds__(352) fused_kernel(
    const float* __restrict__ x, const int* __restrict__ seqL,
    const float* __restrict__ Wmat, const float* __restrict__ p,
    float* __restrict__ out)
{
    __shared__ int sh[3];
    __shared__ __align__(16) float sbuf[8 * HW4 * 4];   // 5.6 KB union
    float4* smax = reinterpret_cast<float4*>(sbuf);     // phase 1
    float*  ws   = sbuf;                                // phase 2: [c][4o] 2 KB
    float*  ypow = sbuf + C_DIM * OSLICE;               // phase 2: [4o][176] 2.8 KB

    int blk = blockIdx.x;
    int b = blk >> 7;            // b-major
    int c = blk & (C_DIM - 1);
    int tid = threadIdx.x;

    // ---- Phase 1: segment max ----
    if (tid == 0) {
        int s0 = 0;
        #pragma unroll
        for (int i = 0; i < B_SEG; i++) s0 += (i < b) ? seqL[i] : 0;
        sh[0] = s0;
        sh[1] = seqL[b];
    }
    __syncthreads();

    {
        int sg  = tid / HW4;
        int col = tid % HW4;
        int s0  = sh[0];
        int len = sh[1];

        const float4* bp = reinterpret_cast<const float4*>(x)
                         + (size_t)c * (S_DIM * HW4) + (size_t)s0 * HW4 + col;

        float4 m = make_float4(NEG_INF, NEG_INF, NEG_INF, NEG_INF);
        int s = sg;
        for (; s + 56 < len; s += 64) {
            float4 a0 = __ldcs(&bp[(size_t)(s +  0) * HW4]);
            float4 a1 = __ldcs(&bp[(size_t)(s +  8) * HW4]);
            float4 a2 = __ldcs(&bp[(size_t)(s + 16) * HW4]);
            float4 a3 = __ldcs(&bp[(size_t)(s + 24) * HW4]);
            float4 a4 = __ldcs(&bp[(size_t)(s + 32) * HW4]);
            float4 a5 = __ldcs(&bp[(size_t)(s + 40) * HW4]);
            float4 a6 = __ldcs(&bp[(size_t)(s + 48) * HW4]);
            float4 a7 = __ldcs(&bp[(size_t)(s + 56) * HW4]);
            m = max4(m, max4(max4(max4(a0, a1), max4(a2, a3)),
                             max4(max4(a4, a5), max4(a6, a7))));
        }
        for (; s < len; s += 8) {
            m = max4(m, __ldcs(&bp[(size_t)s * HW4]));
        }
        smax[sg * HW4 + col] = m;
    }
    __syncthreads();

    if (tid < HW4) {
        float4 r = smax[tid];
        #pragma unroll
        for (int g = 1; g < 8; g++) r = max4(r, smax[g * HW4 + tid]);
        reinterpret_cast<float4*>(g_pooled)[(size_t)(b * C_DIM + c) * HW4 + tid] = r;
    }
    __syncthreads();

    // ---- Publish ----
    if (tid == 0) {
        __threadfence();
        sh[2] = atomicAdd(&g_cnt[b], 1);
    }
    __syncthreads();
    int order = sh[2];
    if (order < C_DIM - NSLICE) return;

    int sl = order - (C_DIM - NSLICE);   // 0..63
    int o0 = sl * OSLICE;

    // Stage W slice [128 c][4 o] while stragglers finish
    for (int i = tid; i < C_DIM * OSLICE; i += 352) {
        int cc = i >> 2;
        int j  = i & (OSLICE - 1);
        ws[i] = Wmat[(o0 + j) * C_DIM + cc];
    }

    if (tid == 0) {
        while (*(volatile int*)&g_cnt[b] != C_DIM) __nanosleep(32);
        __threadfence();
    }
    __syncthreads();

    // ---- Phase 2: conv slice [4 o] x [176 hw] for batch b ----
    {
        int half = tid / HW;        // 0/1 -> o pair
        int hw   = tid % HW;

        unsigned long long acc = 0ULL;
        const float* pb = g_pooled + (size_t)b * C_DIM * HW + hw;
        const float* wh = ws + half * 2;

        #pragma unroll 8
        for (int cc = 0; cc < C_DIM; cc++) {
            unsigned long long pv2 = pack2(__ldg(&pb[(size_t)cc * HW]));
            unsigned long long w =
                *reinterpret_cast<const unsigned long long*>(wh + cc * OSLICE);
            ffma2(acc, pv2, w);
        }

        float pe = __ldg(&p[hw / PART_LEN]);
        bool fast65 = (pe == 6.5f);
        float lo, hi;
        unpack2(acc, lo, hi);
        ypow[(half * 2 + 0) * HW + hw] = gem_pow(lo, pe, fast65);
        ypow[(half * 2 + 1) * HW + hw] = gem_pow(hi, pe, fast65);
    }
    __syncthreads();

    // 16 threads: (o_local, part)
    if (tid < OSLICE * 4) {
        int ol   = tid >> 2;
        int part = tid & 3;
        const float* yp = ypow + ol * HW + part * PART_LEN;
        float sum = 0.0f;
        #pragma unroll
        for (int k = 0; k < PART_LEN; k++) sum += yp[k];
        float pe = __ldg(&p[part]);
        float mean = sum * (1.0f / (float)PART_LEN);
        float gv = (mean > 0.0f) ? exp2f(__log2f(mean) / pe) : 0.0f;
        out[((size_t)b * O_DIM + o0 + ol) * 4 + part] = gv;
    }
}

extern "C" void kernel_launch(void* const* d_in, const int* in_sizes, int n_in,
                              void* d_out, int out_size)
{
    const float* x    = (const float*)d_in[0];
    const int*   seqL = (const int*)d_in[1];
    const float* Wm   = (const float*)d_in[2];
    const float* p    = (const float*)d_in[3];
    float* out = (float*)d_out;

    zero_cnt_kernel<<<1, 32>>>();
    fused_kernel<<<B_SEG * C_DIM, 352>>>(x, seqL, Wm, p, out);
}

// round 16
// speedup vs baseline: 1.0712x; 1.0658x over previous
#include <cuda_runtime.h>
#include <math.h>

#define C_DIM 128
#define S_DIM 4096
#define HW 176          // 16 * 11
#define HW4 44
#define B_SEG 32
#define O_DIM 256
#define OW 32           // o per conv block
#define CPIPE 4
#define PART_LEN 44
#define GEM_EPS 1e-6f
#define NEG_INF -3.402823466e38f

// scratch: pooled[b][c][hw]
__device__ float g_pooled[B_SEG * C_DIM * HW];

__device__ __forceinline__ float4 max4(float4 a, float4 b) {
    float4 r;
    r.x = fmaxf(a.x, b.x); r.y = fmaxf(a.y, b.y);
    r.z = fmaxf(a.z, b.z); r.w = fmaxf(a.w, b.w);
    return r;
}
__device__ __forceinline__ unsigned long long pack2(float v) {
    unsigned long long r;
    asm("mov.b64 %0, {%1, %1};" : "=l"(r) : "f"(v));
    return r;
}
__device__ __forceinline__ void unpack2(unsigned long long v, float& lo, float& hi) {
    asm("mov.b64 {%0, %1}, %2;" : "=f"(lo), "=f"(hi) : "l"(v));
}
__device__ __forceinline__ void ffma2(unsigned long long& d,
                                      unsigned long long a, unsigned long long b) {
    asm("fma.rn.f32x2 %0, %1, %2, %0;" : "+l"(d) : "l"(a), "l"(b));
}
__device__ __forceinline__ void fadd2(unsigned long long& d, unsigned long long a) {
    asm("add.rn.f32x2 %0, %0, %1;" : "+l"(d) : "l"(a));
}
// GeM power, fast path for pe == 6.5: (v^3)^2 * sqrt(v).
__device__ __forceinline__ float gem_pow(float x, float pe, bool fast65) {
    float v = fmaxf(x, GEM_EPS);
    if (fast65) {
        float v3 = v * v * v;
        return v3 * v3 * sqrtf(v);
    }
    return exp2f(pe * __log2f(v));
}

// ---------------------------------------------------------------------------
// Kernel 1: ragged segment max — EXACT R5/R7 config (~59 us, 6.25 TB/s).
// ---------------------------------------------------------------------------
__global__ void __launch_bounds__(352) seg_max_kernel(
    const float* __restrict__ x, const int* __restrict__ seqL)
{
    int blk = blockIdx.x;
    int b = blk & (B_SEG - 1);
    int c = blk >> 5;

    __shared__ int sh[2];
    __shared__ float4 sm[8 * HW4];

    if (threadIdx.x == 0) {
        int s0 = 0;
        #pragma unroll
        for (int i = 0; i < B_SEG; i++) s0 += (i < b) ? seqL[i] : 0;
        sh[0] = s0;
        sh[1] = seqL[b];
    }
    __syncthreads();

    int tid = threadIdx.x;
    int sg  = tid / HW4;
    int col = tid % HW4;

    int s0  = sh[0];
    int len = sh[1];

    const float4* bp = reinterpret_cast<const float4*>(x)
                     + (size_t)c * (S_DIM * HW4) + (size_t)s0 * HW4 + col;

    float4 m = make_float4(NEG_INF, NEG_INF, NEG_INF, NEG_INF);
    int s = sg;
    for (; s + 56 < len; s += 64) {
        float4 a0 = __ldcs(&bp[(size_t)(s +  0) * HW4]);
        float4 a1 = __ldcs(&bp[(size_t)(s +  8) * HW4]);
        float4 a2 = __ldcs(&bp[(size_t)(s + 16) * HW4]);
        float4 a3 = __ldcs(&bp[(size_t)(s + 24) * HW4]);
        float4 a4 = __ldcs(&bp[(size_t)(s + 32) * HW4]);
        float4 a5 = __ldcs(&bp[(size_t)(s + 40) * HW4]);
        float4 a6 = __ldcs(&bp[(size_t)(s + 48) * HW4]);
        float4 a7 = __ldcs(&bp[(size_t)(s + 56) * HW4]);
        m = max4(m, max4(max4(max4(a0, a1), max4(a2, a3)),
                         max4(max4(a4, a5), max4(a6, a7))));
    }
    for (; s < len; s += 8) {
        m = max4(m, __ldcs(&bp[(size_t)s * HW4]));
    }

    sm[sg * HW4 + col] = m;
    __syncthreads();

    if (tid < HW4) {
        float4 r = sm[tid];
        #pragma unroll
        for (int g = 1; g < 8; g++) r = max4(r, sm[g * HW4 + tid]);
        reinterpret_cast<float4*>(g_pooled)[(size_t)(b * C_DIM + c) * HW4 + tid] = r;
    }
}

// ---------------------------------------------------------------------------
// Kernel 2: conv + GeM. OW=32 (min pooled re-reads), 3 loads/32 MACs,
// 352 threads = 2 c-halves x (4 o-groups x 44 hw-quads) -> ~22 warps/SM.
// Grid (8, 32) = 256 blocks. Reduction: half 1 dumps packed acc to smem,
// half 0 merges with add.f32x2, applies gem_pow, then (o, part) reduce.
// ---------------------------------------------------------------------------
__global__ void __launch_bounds__(352) conv_gem_kernel(
    const float* __restrict__ Wmat, const float* __restrict__ p,
    float* __restrict__ out)
{
    __shared__ __align__(16) float ws[C_DIM * OW];            // 16 KB
    __shared__ __align__(16) unsigned long long redu[176 * 16]; // 22.5 KB
    __shared__ float pp[4];
    float* red2 = ws;   // overlay after main loop: [44][32]

    int b   = blockIdx.y;
    int o0  = blockIdx.x * OW;
    int tid = threadIdx.x;
    int ch  = tid / 176;          // c-half 0/1
    int r   = tid % 176;
    int grp = r / HW4;            // o-group 0..3
    int q   = r % HW4;            // hw quad 0..43

    if (tid < 4) pp[tid] = p[tid];
    for (int i = tid; i < C_DIM * OW; i += 352) {
        int cc = i >> 5;
        int j  = i & (OW - 1);
        ws[i] = Wmat[(o0 + j) * C_DIM + cc];
    }
    __syncthreads();

    unsigned long long acc[16];   // [h 0..3][opair 0..3]
    #pragma unroll
    for (int k = 0; k < 16; k++) acc[k] = 0ULL;

    {
        int cbase = ch * 64;
        const float4* pb = reinterpret_cast<const float4*>(
            g_pooled + (size_t)b * C_DIM * HW) + (size_t)cbase * HW4 + q;
        const float* wg = ws + cbase * OW + grp * 8;

        float4 pv[CPIPE];
        #pragma unroll
        for (int j = 0; j < CPIPE; j++)
            pv[j] = __ldg(&pb[(size_t)j * HW4]);

        #pragma unroll
        for (int c0 = 0; c0 < 64; c0 += CPIPE) {
            float4 nv[CPIPE];
            if (c0 + CPIPE < 64) {
                #pragma unroll
                for (int j = 0; j < CPIPE; j++)
                    nv[j] = __ldg(&pb[(size_t)(c0 + CPIPE + j) * HW4]);
            }
            #pragma unroll
            for (int j = 0; j < CPIPE; j++) {
                const ulonglong2* wr = reinterpret_cast<const ulonglong2*>(
                    wg + (c0 + j) * OW);
                ulonglong2 w0 = wr[0];   // o 0..3 of group
                ulonglong2 w1 = wr[1];   // o 4..7 of group
                unsigned long long px = pack2(pv[j].x);
                unsigned long long py = pack2(pv[j].y);
                unsigned long long pz = pack2(pv[j].z);
                unsigned long long pw = pack2(pv[j].w);
                ffma2(acc[ 0], px, w0.x); ffma2(acc[ 1], px, w0.y);
                ffma2(acc[ 2], px, w1.x); ffma2(acc[ 3], px, w1.y);
                ffma2(acc[ 4], py, w0.x); ffma2(acc[ 5], py, w0.y);
                ffma2(acc[ 6], py, w1.x); ffma2(acc[ 7], py, w1.y);
                ffma2(acc[ 8], pz, w0.x); ffma2(acc[ 9], pz, w0.y);
                ffma2(acc[10], pz, w1.x); ffma2(acc[11], pz, w1.y);
                ffma2(acc[12], pw, w0.x); ffma2(acc[13], pw, w0.y);
                ffma2(acc[14], pw, w1.x); ffma2(acc[15], pw, w1.y);
            }
            #pragma unroll
            for (int j = 0; j < CPIPE; j++) pv[j] = nv[j];
        }
    }

    // c-half 1 dumps packed accumulators
    if (ch == 1) {
        ulonglong2* rp = reinterpret_cast<ulonglong2*>(redu + r * 16);
        #pragma unroll
        for (int k = 0; k < 8; k++)
            rp[k] = make_ulonglong2(acc[2 * k], acc[2 * k + 1]);
    }
    __syncthreads();

    // c-half 0 merges, gem_pow, partial-sums over its 4 hw
    if (ch == 0) {
        const ulonglong2* rp = reinterpret_cast<const ulonglong2*>(redu + r * 16);
        #pragma unroll
        for (int k = 0; k < 8; k++) {
            ulonglong2 v = rp[k];
            fadd2(acc[2 * k], v.x);
            fadd2(acc[2 * k + 1], v.y);
        }
        float pe = pp[q / 11];
        bool fast65 = (pe == 6.5f);
        float s[8];
        #pragma unroll
        for (int o = 0; o < 8; o++) s[o] = 0.0f;
        #pragma unroll
        for (int h = 0; h < 4; h++) {
            #pragma unroll
            for (int k = 0; k < 4; k++) {
                float lo, hi;
                unpack2(acc[h * 4 + k], lo, hi);
                s[2 * k + 0] += gem_pow(lo, pe, fast65);
                s[2 * k + 1] += gem_pow(hi, pe, fast65);
            }
        }
        #pragma unroll
        for (int o = 0; o < 8; o++)
            red2[q * OW + grp * 8 + o] = s[o];
    }
    __syncthreads();

    // 128 threads: (o, part) -> sum 11 quad-partials, final root
    if (tid < OW * 4) {
        int o    = tid >> 2;
        int part = tid & 3;
        float sum = 0.0f;
        #pragma unroll
        for (int j = 0; j < 11; j++)
            sum += red2[(part * 11 + j) * OW + o];
        float pe = pp[part];
        float mean = sum * (1.0f / (float)PART_LEN);
        float gv = (mean > 0.0f) ? exp2f(__log2f(mean) / pe) : 0.0f;
        out[((size_t)b * O_DIM + o0 + o) * 4 + part] = gv;
    }
}

extern "C" void kernel_launch(void* const* d_in, const int* in_sizes, int n_in,
                              void* d_out, int out_size)
{
    const float* x    = (const float*)d_in[0];
    const int*   seqL = (const int*)d_in[1];
    const float* Wm   = (const float*)d_in[2];
    const float* p    = (const float*)d_in[3];
    float* out = (float*)d_out;

    seg_max_kernel<<<B_SEG * C_DIM, 352>>>(x, seqL);

    dim3 grid2(O_DIM / OW, B_SEG);
    conv_gem_kernel<<<grid2, 352>>>(Wm, p, out);
}